// round 1
// baseline (speedup 1.0000x reference)
#include <cuda_runtime.h>
#include <cuda_bf16.h>

#define NU 100000
#define NI 100000
#define EE 1600000
#define C  128
#define LN_EPS 1e-5f

// Scratch: static device globals (allocation-free rule).
__device__ float g_sum_u[(size_t)NU * C];
__device__ float g_sum_i[(size_t)NI * C];
__device__ float g_u1[(size_t)NU * C];
__device__ float g_i1[(size_t)NI * C];
__device__ float g_cnt_u[NU];
__device__ float g_cnt_i[NI];

// ---------------------------------------------------------------------------
// Count in-degree per destination node (one thread per edge).
// ---------------------------------------------------------------------------
__global__ void count_kernel(const int* __restrict__ ei_dst,
                             float* __restrict__ cnt, int E) {
    int e = blockIdx.x * blockDim.x + threadIdx.x;
    if (e < E) atomicAdd(&cnt[ei_dst[e]], 1.0f);
}

// ---------------------------------------------------------------------------
// Scatter: one warp per edge. 32 lanes x float4 = 128 channels.
// msgs = x_src[src] * w, accumulated into sum[dst] via vector red (no return).
// ---------------------------------------------------------------------------
__global__ void scatter_kernel(const float* __restrict__ xsrc,
                               const int* __restrict__ ei,
                               const float* __restrict__ ew,
                               float* __restrict__ sum, int E) {
    int gw   = (blockIdx.x * blockDim.x + threadIdx.x) >> 5;
    int lane = threadIdx.x & 31;
    if (gw >= E) return;

    int   src = __ldg(ei + gw);
    int   dst = __ldg(ei + E + gw);
    float w   = __ldg(ew + gw);

    float4 v = __ldg(reinterpret_cast<const float4*>(xsrc + (size_t)src * C) + lane);
    v.x *= w; v.y *= w; v.z *= w; v.w *= w;

    float* d = sum + (size_t)dst * C + lane * 4;
    asm volatile("red.global.add.v4.f32 [%0], {%1, %2, %3, %4};"
                 :: "l"(d), "f"(v.x), "f"(v.y), "f"(v.z), "f"(v.w)
                 : "memory");
}

// ---------------------------------------------------------------------------
// Combine: one warp per node.
//   v = sum/max(cnt,1) + x_dst ; LayerNorm(v)*w + b ; optional ReLU.
// ---------------------------------------------------------------------------
__global__ void combine_kernel(const float* __restrict__ sum,
                               const float* __restrict__ cnt,
                               const float* __restrict__ xdst,
                               const float* __restrict__ lnw,
                               const float* __restrict__ lnb,
                               float* __restrict__ out, int N, int do_relu) {
    int gw   = (blockIdx.x * blockDim.x + threadIdx.x) >> 5;
    int lane = threadIdx.x & 31;
    if (gw >= N) return;

    float rc = 1.0f / fmaxf(__ldg(cnt + gw), 1.0f);

    float4 s = *(reinterpret_cast<const float4*>(sum  + (size_t)gw * C) + lane);
    float4 x = __ldg(reinterpret_cast<const float4*>(xdst + (size_t)gw * C) + lane);

    float4 v;
    v.x = fmaf(s.x, rc, x.x);
    v.y = fmaf(s.y, rc, x.y);
    v.z = fmaf(s.z, rc, x.z);
    v.w = fmaf(s.w, rc, x.w);

    // mean
    float m = v.x + v.y + v.z + v.w;
#pragma unroll
    for (int o = 16; o > 0; o >>= 1) m += __shfl_xor_sync(0xffffffffu, m, o);
    m *= (1.0f / C);

    float4 d;
    d.x = v.x - m; d.y = v.y - m; d.z = v.z - m; d.w = v.w - m;

    // variance
    float var = d.x * d.x + d.y * d.y + d.z * d.z + d.w * d.w;
#pragma unroll
    for (int o = 16; o > 0; o >>= 1) var += __shfl_xor_sync(0xffffffffu, var, o);
    var *= (1.0f / C);

    float inv = rsqrtf(var + LN_EPS);

    float4 wv = __ldg(reinterpret_cast<const float4*>(lnw) + lane);
    float4 bv = __ldg(reinterpret_cast<const float4*>(lnb) + lane);

    float4 o4;
    o4.x = fmaf(d.x * inv, wv.x, bv.x);
    o4.y = fmaf(d.y * inv, wv.y, bv.y);
    o4.z = fmaf(d.z * inv, wv.z, bv.z);
    o4.w = fmaf(d.w * inv, wv.w, bv.w);

    if (do_relu) {
        o4.x = fmaxf(o4.x, 0.0f);
        o4.y = fmaxf(o4.y, 0.0f);
        o4.z = fmaxf(o4.z, 0.0f);
        o4.w = fmaxf(o4.w, 0.0f);
    }

    *(reinterpret_cast<float4*>(out + (size_t)gw * C) + lane) = o4;
}

extern "C" void kernel_launch(void* const* d_in, const int* in_sizes, int n_in,
                              void* d_out, int out_size) {
    const float* x_user = (const float*)d_in[0];
    const float* x_item = (const float*)d_in[1];
    const float* ew_ui  = (const float*)d_in[2];
    const float* ew_iu  = (const float*)d_in[3];
    const float* lnwu0  = (const float*)d_in[4];
    const float* lnbu0  = (const float*)d_in[5];
    const float* lnwu1  = (const float*)d_in[6];
    const float* lnbu1  = (const float*)d_in[7];
    const float* lnwi0  = (const float*)d_in[8];
    const float* lnbi0  = (const float*)d_in[9];
    const float* lnwi1  = (const float*)d_in[10];
    const float* lnbi1  = (const float*)d_in[11];
    const int*   ei_ui  = (const int*)d_in[12];
    const int*   ei_iu  = (const int*)d_in[13];
    float*       out    = (float*)d_out;

    float *sum_u, *sum_i, *u1, *i1, *cnt_u, *cnt_i;
    cudaGetSymbolAddress((void**)&sum_u, g_sum_u);
    cudaGetSymbolAddress((void**)&sum_i, g_sum_i);
    cudaGetSymbolAddress((void**)&u1,    g_u1);
    cudaGetSymbolAddress((void**)&i1,    g_i1);
    cudaGetSymbolAddress((void**)&cnt_u, g_cnt_u);
    cudaGetSymbolAddress((void**)&cnt_i, g_cnt_i);

    const int CNT_BLK  = 256;
    const int CNT_GRID = (EE + CNT_BLK - 1) / CNT_BLK;
    const int SC_GRID  = EE / 8;   // one warp per edge, 8 warps/block
    const int CU_GRID  = NU / 8;   // one warp per node
    const int CI_GRID  = NI / 8;

    // degree counts (layer-invariant)
    cudaMemsetAsync(cnt_u, 0, NU * sizeof(float));
    cudaMemsetAsync(cnt_i, 0, NI * sizeof(float));
    count_kernel<<<CNT_GRID, CNT_BLK>>>(ei_iu + EE, cnt_u, EE);
    count_kernel<<<CNT_GRID, CNT_BLK>>>(ei_ui + EE, cnt_i, EE);

    // ---- layer 0 ----
    cudaMemsetAsync(sum_u, 0, (size_t)NU * C * sizeof(float));
    cudaMemsetAsync(sum_i, 0, (size_t)NI * C * sizeof(float));
    scatter_kernel<<<SC_GRID, 256>>>(x_item, ei_iu, ew_iu, sum_u, EE);
    scatter_kernel<<<SC_GRID, 256>>>(x_user, ei_ui, ew_ui, sum_i, EE);
    combine_kernel<<<CU_GRID, 256>>>(sum_u, cnt_u, x_user, lnwu0, lnbu0, u1, NU, 1);
    combine_kernel<<<CI_GRID, 256>>>(sum_i, cnt_i, x_item, lnwi0, lnbi0, i1, NI, 1);

    // ---- layer 1 ----
    cudaMemsetAsync(sum_u, 0, (size_t)NU * C * sizeof(float));
    cudaMemsetAsync(sum_i, 0, (size_t)NI * C * sizeof(float));
    scatter_kernel<<<SC_GRID, 256>>>(i1, ei_iu, ew_iu, sum_u, EE);
    scatter_kernel<<<SC_GRID, 256>>>(u1, ei_ui, ew_ui, sum_i, EE);
    combine_kernel<<<CU_GRID, 256>>>(sum_u, cnt_u, u1, lnwu1, lnbu1,
                                     out, NU, 0);
    combine_kernel<<<CI_GRID, 256>>>(sum_i, cnt_i, i1, lnwi1, lnbi1,
                                     out + (size_t)NU * C, NI, 0);
}

// round 2
// speedup vs baseline: 3.1042x; 3.1042x over previous
#include <cuda_runtime.h>
#include <cuda_bf16.h>

#define NU 100000
#define NI 100000
#define EE 1600000
#define C  128
#define LN_EPS 1e-5f

#define SCAN_T     256
#define SCAN_E     4
#define SCAN_CHUNK (SCAN_T * SCAN_E)   // 1024
#define NB_U ((NU + SCAN_CHUNK - 1) / SCAN_CHUNK)   // 98
#define NB_I ((NI + SCAN_CHUNK - 1) / SCAN_CHUNK)

// ---- scratch (allocation-free rule: device globals) ----
__device__ int   g_deg_u[NU];
__device__ int   g_deg_i[NI];
__device__ int   g_off_u[NU + 1];
__device__ int   g_off_i[NI + 1];
__device__ int   g_cur_u[NU];
__device__ int   g_cur_i[NI];
__device__ int   g_bsum_u[NB_U];
__device__ int   g_bsum_i[NB_I];
__device__ int2  g_csr_iu[EE];   // edges into user nodes: {src_item, w}
__device__ int2  g_csr_ui[EE];   // edges into item nodes: {src_user, w}
__device__ float g_u1[(size_t)NU * C];
__device__ float g_i1[(size_t)NI * C];

// ---------------------------------------------------------------------------
// 1) in-degree histogram
// ---------------------------------------------------------------------------
__global__ void count_kernel(const int* __restrict__ ei_dst,
                             int* __restrict__ deg, int E) {
    int e = blockIdx.x * blockDim.x + threadIdx.x;
    if (e < E) atomicAdd(&deg[ei_dst[e]], 1);
}

// ---------------------------------------------------------------------------
// 2) exclusive prefix scan (3 kernels)
// ---------------------------------------------------------------------------
__global__ void scan1_kernel(const int* __restrict__ in, int* __restrict__ out,
                             int* __restrict__ bsum, int N) {
    __shared__ int sh[SCAN_T];
    int base = blockIdx.x * SCAN_CHUNK + threadIdx.x * SCAN_E;
    int v[SCAN_E];
    int s = 0;
#pragma unroll
    for (int i = 0; i < SCAN_E; i++) {
        int idx = base + i;
        v[i] = (idx < N) ? in[idx] : 0;
        s += v[i];
    }
    sh[threadIdx.x] = s;
    __syncthreads();
    for (int o = 1; o < SCAN_T; o <<= 1) {
        int val = sh[threadIdx.x];
        int add = (threadIdx.x >= o) ? sh[threadIdx.x - o] : 0;
        __syncthreads();
        sh[threadIdx.x] = val + add;
        __syncthreads();
    }
    int run = sh[threadIdx.x] - s;   // exclusive prefix of this thread
#pragma unroll
    for (int i = 0; i < SCAN_E; i++) {
        int idx = base + i;
        if (idx < N) out[idx] = run;
        run += v[i];
    }
    if (threadIdx.x == SCAN_T - 1) bsum[blockIdx.x] = sh[SCAN_T - 1];
}

__global__ void scan2_kernel(int* __restrict__ bsum, int nb) {
    __shared__ int sh[256];
    int t = threadIdx.x;
    sh[t] = (t < nb) ? bsum[t] : 0;
    __syncthreads();
    if (t == 0) {
        int run = 0;
        for (int i = 0; i < nb; i++) { int x = sh[i]; sh[i] = run; run += x; }
    }
    __syncthreads();
    if (t < nb) bsum[t] = sh[t];
}

__global__ void scan3_kernel(int* __restrict__ out, const int* __restrict__ bsum,
                             int N, int total) {
    int i = blockIdx.x * blockDim.x + threadIdx.x;
    if (i < N) out[i] += bsum[i / SCAN_CHUNK];
    if (i == 0) out[N] = total;
}

// ---------------------------------------------------------------------------
// 3) CSR fill: group edges by destination
// ---------------------------------------------------------------------------
__global__ void fill_csr_kernel(const int* __restrict__ ei,
                                const float* __restrict__ ew,
                                int* __restrict__ cursor,
                                int2* __restrict__ csr, int E) {
    int e = blockIdx.x * blockDim.x + threadIdx.x;
    if (e >= E) return;
    int   src = ei[e];
    int   dst = ei[E + e];
    float w   = ew[e];
    int pos = atomicAdd(&cursor[dst], 1);
    csr[pos] = make_int2(src, __float_as_int(w));
}

// ---------------------------------------------------------------------------
// 4) fused gather + mean + root + LayerNorm (+ReLU). One warp per dst node.
// ---------------------------------------------------------------------------
__global__ void gather_combine_kernel(const int* __restrict__ off,
                                      const int2* __restrict__ csr,
                                      const float* __restrict__ xsrc,
                                      const float* __restrict__ xdst,
                                      const float* __restrict__ lnw,
                                      const float* __restrict__ lnb,
                                      float* __restrict__ out,
                                      int N, int do_relu) {
    int gw   = (blockIdx.x * blockDim.x + threadIdx.x) >> 5;
    int lane = threadIdx.x & 31;
    if (gw >= N) return;

    int beg = __ldg(off + gw);
    int end = __ldg(off + gw + 1);

    float4 acc = make_float4(0.f, 0.f, 0.f, 0.f);
    int e = beg;
    for (; e + 1 < end; e += 2) {
        int2 p0 = __ldg(csr + e);
        int2 p1 = __ldg(csr + e + 1);
        float4 v0 = __ldg(reinterpret_cast<const float4*>(xsrc + (size_t)p0.x * C) + lane);
        float4 v1 = __ldg(reinterpret_cast<const float4*>(xsrc + (size_t)p1.x * C) + lane);
        float w0 = __int_as_float(p0.y);
        float w1 = __int_as_float(p1.y);
        acc.x = fmaf(w0, v0.x, acc.x); acc.y = fmaf(w0, v0.y, acc.y);
        acc.z = fmaf(w0, v0.z, acc.z); acc.w = fmaf(w0, v0.w, acc.w);
        acc.x = fmaf(w1, v1.x, acc.x); acc.y = fmaf(w1, v1.y, acc.y);
        acc.z = fmaf(w1, v1.z, acc.z); acc.w = fmaf(w1, v1.w, acc.w);
    }
    if (e < end) {
        int2 p0 = __ldg(csr + e);
        float4 v0 = __ldg(reinterpret_cast<const float4*>(xsrc + (size_t)p0.x * C) + lane);
        float w0 = __int_as_float(p0.y);
        acc.x = fmaf(w0, v0.x, acc.x); acc.y = fmaf(w0, v0.y, acc.y);
        acc.z = fmaf(w0, v0.z, acc.z); acc.w = fmaf(w0, v0.w, acc.w);
    }

    float rc = 1.0f / fmaxf((float)(end - beg), 1.0f);

    float4 x = __ldg(reinterpret_cast<const float4*>(xdst + (size_t)gw * C) + lane);
    float4 v;
    v.x = fmaf(acc.x, rc, x.x);
    v.y = fmaf(acc.y, rc, x.y);
    v.z = fmaf(acc.z, rc, x.z);
    v.w = fmaf(acc.w, rc, x.w);

    // mean
    float m = v.x + v.y + v.z + v.w;
#pragma unroll
    for (int o = 16; o > 0; o >>= 1) m += __shfl_xor_sync(0xffffffffu, m, o);
    m *= (1.0f / C);

    float4 d;
    d.x = v.x - m; d.y = v.y - m; d.z = v.z - m; d.w = v.w - m;

    // variance
    float var = d.x * d.x + d.y * d.y + d.z * d.z + d.w * d.w;
#pragma unroll
    for (int o = 16; o > 0; o >>= 1) var += __shfl_xor_sync(0xffffffffu, var, o);
    var *= (1.0f / C);

    float inv = rsqrtf(var + LN_EPS);

    float4 wv = __ldg(reinterpret_cast<const float4*>(lnw) + lane);
    float4 bv = __ldg(reinterpret_cast<const float4*>(lnb) + lane);

    float4 o4;
    o4.x = fmaf(d.x * inv, wv.x, bv.x);
    o4.y = fmaf(d.y * inv, wv.y, bv.y);
    o4.z = fmaf(d.z * inv, wv.z, bv.z);
    o4.w = fmaf(d.w * inv, wv.w, bv.w);

    if (do_relu) {
        o4.x = fmaxf(o4.x, 0.0f);
        o4.y = fmaxf(o4.y, 0.0f);
        o4.z = fmaxf(o4.z, 0.0f);
        o4.w = fmaxf(o4.w, 0.0f);
    }

    *(reinterpret_cast<float4*>(out + (size_t)gw * C) + lane) = o4;
}

extern "C" void kernel_launch(void* const* d_in, const int* in_sizes, int n_in,
                              void* d_out, int out_size) {
    const float* x_user = (const float*)d_in[0];
    const float* x_item = (const float*)d_in[1];
    const float* ew_ui  = (const float*)d_in[2];
    const float* ew_iu  = (const float*)d_in[3];
    const float* lnwu0  = (const float*)d_in[4];
    const float* lnbu0  = (const float*)d_in[5];
    const float* lnwu1  = (const float*)d_in[6];
    const float* lnbu1  = (const float*)d_in[7];
    const float* lnwi0  = (const float*)d_in[8];
    const float* lnbi0  = (const float*)d_in[9];
    const float* lnwi1  = (const float*)d_in[10];
    const float* lnbi1  = (const float*)d_in[11];
    const int*   ei_ui  = (const int*)d_in[12];
    const int*   ei_iu  = (const int*)d_in[13];
    float*       out    = (float*)d_out;

    int *deg_u, *deg_i, *off_u, *off_i, *cur_u, *cur_i, *bsum_u, *bsum_i;
    int2 *csr_iu, *csr_ui;
    float *u1, *i1;
    cudaGetSymbolAddress((void**)&deg_u, g_deg_u);
    cudaGetSymbolAddress((void**)&deg_i, g_deg_i);
    cudaGetSymbolAddress((void**)&off_u, g_off_u);
    cudaGetSymbolAddress((void**)&off_i, g_off_i);
    cudaGetSymbolAddress((void**)&cur_u, g_cur_u);
    cudaGetSymbolAddress((void**)&cur_i, g_cur_i);
    cudaGetSymbolAddress((void**)&bsum_u, g_bsum_u);
    cudaGetSymbolAddress((void**)&bsum_i, g_bsum_i);
    cudaGetSymbolAddress((void**)&csr_iu, g_csr_iu);
    cudaGetSymbolAddress((void**)&csr_ui, g_csr_ui);
    cudaGetSymbolAddress((void**)&u1, g_u1);
    cudaGetSymbolAddress((void**)&i1, g_i1);

    const int EB   = 256;
    const int EG   = (EE + EB - 1) / EB;
    const int GC_U = NU / 8;     // warp per node, 8 warps/block
    const int GC_I = NI / 8;

    // ---- CSR build (layer-invariant; reused by both layers) ----
    cudaMemsetAsync(deg_u, 0, NU * sizeof(int));
    cudaMemsetAsync(deg_i, 0, NI * sizeof(int));
    count_kernel<<<EG, EB>>>(ei_iu + EE, deg_u, EE);
    count_kernel<<<EG, EB>>>(ei_ui + EE, deg_i, EE);

    scan1_kernel<<<NB_U, SCAN_T>>>(deg_u, off_u, bsum_u, NU);
    scan2_kernel<<<1, 256>>>(bsum_u, NB_U);
    scan3_kernel<<<(NU + 255) / 256, 256>>>(off_u, bsum_u, NU, EE);

    scan1_kernel<<<NB_I, SCAN_T>>>(deg_i, off_i, bsum_i, NI);
    scan2_kernel<<<1, 256>>>(bsum_i, NB_I);
    scan3_kernel<<<(NI + 255) / 256, 256>>>(off_i, bsum_i, NI, EE);

    cudaMemcpyAsync(cur_u, off_u, NU * sizeof(int), cudaMemcpyDeviceToDevice);
    cudaMemcpyAsync(cur_i, off_i, NI * sizeof(int), cudaMemcpyDeviceToDevice);
    fill_csr_kernel<<<EG, EB>>>(ei_iu, ew_iu, cur_u, csr_iu, EE);
    fill_csr_kernel<<<EG, EB>>>(ei_ui, ew_ui, cur_i, csr_ui, EE);

    // ---- layer 0 ----
    gather_combine_kernel<<<GC_U, 256>>>(off_u, csr_iu, x_item, x_user,
                                         lnwu0, lnbu0, u1, NU, 1);
    gather_combine_kernel<<<GC_I, 256>>>(off_i, csr_ui, x_user, x_item,
                                         lnwi0, lnbi0, i1, NI, 1);

    // ---- layer 1 ----
    gather_combine_kernel<<<GC_U, 256>>>(off_u, csr_iu, i1, u1,
                                         lnwu1, lnbu1, out, NU, 0);
    gather_combine_kernel<<<GC_I, 256>>>(off_i, csr_ui, u1, i1,
                                         lnwi1, lnbi1, out + (size_t)NU * C, NI, 0);
}